// round 3
// baseline (speedup 1.0000x reference)
#include <cuda_runtime.h>

// StackMemory: reference scan only writes stack row 0 and reads row 1 (always
// zero), so:
//   out[0, t, 0, h] = softmax0(hs[t]·W^T + b) * sigmoid(hs[t]·D)  (all h equal)
//   out[0, t, d, h] = 0 for d >= 1
//
// One launch, two block roles:
//   blocks [0, T/32): compute. warp-per-t (4 t per warp), butterfly reduce,
//                     writes the 100-float4 val row for each t. ~26 MB traffic.
//   blocks [T/32, T/32+T): pure streaming zero-fill of the d>=1 region,
//                     FULLY UNROLLED: 12 unconditional STG.128 + 1 tail store.

#define HID    400
#define DEPTH  32
#define ROW4   (DEPTH * HID / 4)   // 3200 float4 per timestep
#define VAL4   (HID / 4)           // 100 float4 val row
#define ZERO4  (ROW4 - VAL4)       // 3100 float4 zero region per timestep
#define TPB    256

__global__ void __launch_bounds__(TPB, 8)
stackmem_kernel(const float* __restrict__ hs,
                const float* __restrict__ W,
                const float* __restrict__ b,
                const float* __restrict__ Dv,
                float* __restrict__ out,
                int n_compute_blocks) {
    if ((int)blockIdx.x >= n_compute_blocks) {
        // ---------- pure zero-fill role: straight-line store burst ----------
        const int t = blockIdx.x - n_compute_blocks;
        float4* __restrict__ o4 =
            reinterpret_cast<float4*>(out + (size_t)t * (DEPTH * HID)) + VAL4
            + threadIdx.x;
        const float4 zz = make_float4(0.f, 0.f, 0.f, 0.f);
        // ZERO4 = 3100 = 12*256 + 28
        #pragma unroll
        for (int j = 0; j < 12; j++) {
            __stcs(o4 + j * TPB, zz);
        }
        if (threadIdx.x < (ZERO4 - 12 * TPB)) {
            __stcs(o4 + 12 * TPB, zz);
        }
        return;
    }

    // ---------- compute role: warp per t, 4 t per warp ----------
    const int wid  = threadIdx.x >> 5;
    const int lane = threadIdx.x & 31;
    const int t0   = blockIdx.x * 32 + wid * 4;

    const float4* __restrict__ w0 = reinterpret_cast<const float4*>(W);
    const float4* __restrict__ w1 = reinterpret_cast<const float4*>(W + HID);
    const float4* __restrict__ w2 = reinterpret_cast<const float4*>(W + 2 * HID);
    const float4* __restrict__ d4 = reinterpret_cast<const float4*>(Dv);
    const float b0 = __ldg(&b[0]), b1 = __ldg(&b[1]), b2 = __ldg(&b[2]);

    #pragma unroll
    for (int k = 0; k < 4; k++) {
        const int t = t0 + k;
        const float4* __restrict__ x4 =
            reinterpret_cast<const float4*>(hs + (size_t)t * HID);

        float a0 = 0.f, a1 = 0.f, a2 = 0.f, a3 = 0.f;
        // VAL4 = 100; lanes 0..31 -> iters at i, i+32, i+64, (i+96 if lane<4)
        for (int i = lane; i < VAL4; i += 32) {
            float4 x = __ldg(&x4[i]);
            float4 p;
            p = __ldg(&w0[i]); a0 += x.x*p.x + x.y*p.y + x.z*p.z + x.w*p.w;
            p = __ldg(&w1[i]); a1 += x.x*p.x + x.y*p.y + x.z*p.z + x.w*p.w;
            p = __ldg(&w2[i]); a2 += x.x*p.x + x.y*p.y + x.z*p.z + x.w*p.w;
            p = __ldg(&d4[i]); a3 += x.x*p.x + x.y*p.y + x.z*p.z + x.w*p.w;
        }

        // Butterfly reduce: every lane ends with the full sum (no broadcast).
        #pragma unroll
        for (int o = 16; o > 0; o >>= 1) {
            a0 += __shfl_xor_sync(0xFFFFFFFFu, a0, o);
            a1 += __shfl_xor_sync(0xFFFFFFFFu, a1, o);
            a2 += __shfl_xor_sync(0xFFFFFFFFu, a2, o);
            a3 += __shfl_xor_sync(0xFFFFFFFFu, a3, o);
        }

        const float l0 = a0 + b0, l1 = a1 + b1, l2 = a2 + b2;
        const float m  = fmaxf(l0, fmaxf(l1, l2));
        const float e0 = __expf(l0 - m);
        const float e1 = __expf(l1 - m);
        const float e2 = __expf(l2 - m);
        const float p0 = e0 / (e0 + e1 + e2);
        const float pv = 1.0f / (1.0f + __expf(-a3));
        const float v  = p0 * pv;
        const float4 vv = make_float4(v, v, v, v);

        float4* __restrict__ o4 =
            reinterpret_cast<float4*>(out + (size_t)t * (DEPTH * HID));
        #pragma unroll
        for (int j = 0; j < 3; j++) {
            __stcs(&o4[lane + j * 32], vv);
        }
        if (lane < VAL4 - 96) {
            __stcs(&o4[lane + 96], vv);
        }
    }
}

extern "C" void kernel_launch(void* const* d_in, const int* in_sizes, int n_in,
                              void* d_out, int out_size) {
    const float* hs = (const float*)d_in[0];   // (1, T, 400)
    const float* W  = (const float*)d_in[1];   // (3, 400)
    const float* b  = (const float*)d_in[2];   // (3,)
    const float* Dv = (const float*)d_in[3];   // (1, 400)
    float* out = (float*)d_out;                // (1, T, 32, 400)

    const int T = in_sizes[0] / HID;           // 8192 (B=1)
    const int n_compute = T / 32;              // 256 compute blocks (warp x4 t)
    stackmem_kernel<<<n_compute + T, TPB>>>(hs, W, b, Dv, out, n_compute);
}

// round 4
// speedup vs baseline: 1.3525x; 1.3525x over previous
#include <cuda_runtime.h>

// StackMemory: reference scan only writes stack row 0 and reads row 1 (always
// zero), so:
//   out[0, t, 0, h] = softmax0(hs[t]·W^T + b) * sigmoid(hs[t]·D)  (all h equal)
//   out[0, t, d, h] = 0 for d >= 1
//
// One launch, two block roles:
//   blocks [0, T/32): compute. warp-per-t (4 t per warp), butterfly reduce,
//                     writes the 100-float4 val row for each t. ~26 MB traffic.
//   blocks [T/32, T/32+T/2): zero-fill, 2 timesteps per block, strided loop
//                     with unroll 4 (paced store stream — R3 showed that a
//                     fully-unrolled 12-store burst saturates the L1tex
//                     wavefront queue and starves HBM: 63->87us regression).

#define HID    400
#define DEPTH  32
#define ROW4   (DEPTH * HID / 4)   // 3200 float4 per timestep
#define VAL4   (HID / 4)           // 100 float4 val row
#define ZERO4  (ROW4 - VAL4)       // 3100 float4 zero region per timestep
#define TPB    256

__global__ void __launch_bounds__(TPB, 8)
stackmem_kernel(const float* __restrict__ hs,
                const float* __restrict__ W,
                const float* __restrict__ b,
                const float* __restrict__ Dv,
                float* __restrict__ out,
                int n_compute_blocks) {
    if ((int)blockIdx.x >= n_compute_blocks) {
        // ---------- zero-fill role: 2 timesteps per block, paced loop ----------
        const int t0 = (blockIdx.x - n_compute_blocks) * 2;
        const float4 zz = make_float4(0.f, 0.f, 0.f, 0.f);
        #pragma unroll
        for (int k = 0; k < 2; k++) {
            float4* __restrict__ o4 =
                reinterpret_cast<float4*>(out + (size_t)(t0 + k) * (DEPTH * HID))
                + VAL4;
            #pragma unroll 4
            for (int i = threadIdx.x; i < ZERO4; i += TPB) {
                __stcs(&o4[i], zz);
            }
        }
        return;
    }

    // ---------- compute role: warp per t, 4 t per warp ----------
    const int wid  = threadIdx.x >> 5;
    const int lane = threadIdx.x & 31;
    const int t0   = blockIdx.x * 32 + wid * 4;

    const float4* __restrict__ w0 = reinterpret_cast<const float4*>(W);
    const float4* __restrict__ w1 = reinterpret_cast<const float4*>(W + HID);
    const float4* __restrict__ w2 = reinterpret_cast<const float4*>(W + 2 * HID);
    const float4* __restrict__ d4 = reinterpret_cast<const float4*>(Dv);
    const float b0 = __ldg(&b[0]), b1 = __ldg(&b[1]), b2 = __ldg(&b[2]);

    #pragma unroll
    for (int k = 0; k < 4; k++) {
        const int t = t0 + k;
        const float4* __restrict__ x4 =
            reinterpret_cast<const float4*>(hs + (size_t)t * HID);

        float a0 = 0.f, a1 = 0.f, a2 = 0.f, a3 = 0.f;
        for (int i = lane; i < VAL4; i += 32) {
            float4 x = __ldg(&x4[i]);
            float4 p;
            p = __ldg(&w0[i]); a0 += x.x*p.x + x.y*p.y + x.z*p.z + x.w*p.w;
            p = __ldg(&w1[i]); a1 += x.x*p.x + x.y*p.y + x.z*p.z + x.w*p.w;
            p = __ldg(&w2[i]); a2 += x.x*p.x + x.y*p.y + x.z*p.z + x.w*p.w;
            p = __ldg(&d4[i]); a3 += x.x*p.x + x.y*p.y + x.z*p.z + x.w*p.w;
        }

        // Butterfly reduce: every lane ends with the full sum (no broadcast).
        #pragma unroll
        for (int o = 16; o > 0; o >>= 1) {
            a0 += __shfl_xor_sync(0xFFFFFFFFu, a0, o);
            a1 += __shfl_xor_sync(0xFFFFFFFFu, a1, o);
            a2 += __shfl_xor_sync(0xFFFFFFFFu, a2, o);
            a3 += __shfl_xor_sync(0xFFFFFFFFu, a3, o);
        }

        const float l0 = a0 + b0, l1 = a1 + b1, l2 = a2 + b2;
        const float m  = fmaxf(l0, fmaxf(l1, l2));
        const float e0 = __expf(l0 - m);
        const float e1 = __expf(l1 - m);
        const float e2 = __expf(l2 - m);
        const float p0 = e0 / (e0 + e1 + e2);
        const float pv = 1.0f / (1.0f + __expf(-a3));
        const float v  = p0 * pv;
        const float4 vv = make_float4(v, v, v, v);

        float4* __restrict__ o4 =
            reinterpret_cast<float4*>(out + (size_t)t * (DEPTH * HID));
        for (int i = lane; i < VAL4; i += 32) {
            __stcs(&o4[i], vv);
        }
    }
}

extern "C" void kernel_launch(void* const* d_in, const int* in_sizes, int n_in,
                              void* d_out, int out_size) {
    const float* hs = (const float*)d_in[0];   // (1, T, 400)
    const float* W  = (const float*)d_in[1];   // (3, 400)
    const float* b  = (const float*)d_in[2];   // (3,)
    const float* Dv = (const float*)d_in[3];   // (1, 400)
    float* out = (float*)d_out;                // (1, T, 32, 400)

    const int T = in_sizes[0] / HID;           // 8192 (B=1)
    const int n_compute = T / 32;              // 256 compute blocks
    const int n_fill    = T / 2;               // 4096 fill blocks (2 t each)
    stackmem_kernel<<<n_compute + n_fill, TPB>>>(hs, W, b, Dv, out, n_compute);
}